// round 10
// baseline (speedup 1.0000x reference)
#include <cuda_runtime.h>
#include <cuda_bf16.h>
#include <math.h>
#include <stdint.h>

// Problem constants
#define N_TOKENS   32768
#define HIDDEN     2048
#define N_EXPERTS  256
#define N_GROUP    8
#define TOPK_GROUP 4
#define TOP_K      8
#define ROUTED_SCALING 2.5f

// margin thresholds (score space); draft score error ~1e-6
#define TAU_E 1e-4f
#define TAU_G 2e-4f
#define FIX_GRID 1024

// device scratch (no allocation allowed) — 16B aligned for vector access
__device__ int d_fix_count;
__device__ int d_fix_list[N_TOKENS];
__device__ __align__(16) __nv_bfloat16 d_b0[N_EXPERTS * HIDDEN];
__device__ __align__(16) __nv_bfloat16 d_b1[N_EXPERTS * HIDDEN];

// ---------------------------------------------------------------------------
// XLA CPU GenerateVF32Exp (Cephes) — bit-pinned (reference sigmoid).
// ---------------------------------------------------------------------------
__device__ __forceinline__ float xla_expf(float v) {
    float x = fminf(fmaxf(v, -88.3762626647949f), 88.3762626647950f);
    float fx = floorf(fmaf(x, 1.44269504088896341f, 0.5f));
    float tmp = __fmul_rn(fx, 0.693359375f);
    float z2  = __fmul_rn(fx, -2.12194440e-4f);
    x = __fsub_rn(x, tmp);
    x = __fsub_rn(x, z2);
    float zz = __fmul_rn(x, x);
    float y = 1.9875691500E-4f;
    y = fmaf(y, x, 1.3981999507E-3f);
    y = fmaf(y, x, 8.3334519073E-3f);
    y = fmaf(y, x, 4.1665795894E-2f);
    y = fmaf(y, x, 1.6666665459E-1f);
    y = fmaf(y, x, 5.0000001201E-1f);
    y = fmaf(y, zz, x);
    y = __fadd_rn(y, 1.0f);
    int n = (int)fx;
    float p2n = __int_as_float((n + 127) << 23);
    return __fmul_rn(y, p2n);
}

__device__ __forceinline__ float ref_sigmoid(float L) {
    return __fdiv_rn(1.0f, __fadd_rn(1.0f, xla_expf(-L)));
}

// ---------------------------------------------------------------------------
// mma.sync helpers (bf16 m16n8k16, fp32 accum)
// ---------------------------------------------------------------------------
__device__ __forceinline__ void ldsm_x4(uint32_t& r0, uint32_t& r1,
                                        uint32_t& r2, uint32_t& r3, uint32_t addr) {
    asm volatile("ldmatrix.sync.aligned.m8n8.x4.shared.b16 {%0,%1,%2,%3},[%4];"
                 : "=r"(r0), "=r"(r1), "=r"(r2), "=r"(r3) : "r"(addr));
}
__device__ __forceinline__ void mma16816(float* c, const uint32_t* a,
                                         uint32_t b0, uint32_t b1) {
    asm volatile(
        "mma.sync.aligned.m16n8k16.row.col.f32.bf16.bf16.f32 "
        "{%0,%1,%2,%3},{%4,%5,%6,%7},{%8,%9},{%0,%1,%2,%3};"
        : "+f"(c[0]), "+f"(c[1]), "+f"(c[2]), "+f"(c[3])
        : "r"(a[0]), "r"(a[1]), "r"(a[2]), "r"(a[3]), "r"(b0), "r"(b1));
}

// ---------------------------------------------------------------------------
__global__ void reset_kernel() { d_fix_count = 0; }

// Split B (weights) into bf16 hi/lo once.  256*2048/4 = 131072 float4.
__global__ __launch_bounds__(256)
void split_b_kernel(const float* __restrict__ B) {
    int i = blockIdx.x * 256 + threadIdx.x;      // 0..131071
    const float4* b4 = (const float4*)B;
    float4 v = b4[i];
    float f[4] = {v.x, v.y, v.z, v.w};
#pragma unroll
    for (int j = 0; j < 4; j++) {
        __nv_bfloat16 h0 = __float2bfloat16_rn(f[j]);
        float r = f[j] - __bfloat162float(h0);
        __nv_bfloat16 h1 = __float2bfloat16_rn(r);
        d_b0[i * 4 + j] = h0;
        d_b1[i * 4 + j] = h1;
    }
}

// ---------------------------------------------------------------------------
// Draft GEMM: C[M,256] = A[M,K]*B[256,K]^T via bf16 3-product split.
// BM=64 rows per block, BN=256 (all experts), BK=32. 256 threads = 8 warps.
// Warp (wm 0-1, wn 0-3): 32 rows x 64 cols = 2 m-tiles x 8 n-tiles (16x8).
// A_ST=40 bf16 (80 B/row): 16B-aligned rows for ldmatrix; banks (20r)%32
// distinct for r=0..7 -> conflict-free.
// ---------------------------------------------------------------------------
#define BMD 64
#define BKD 32
#define A_ST 40
#define AS0_OFF 0
#define AS1_OFF (64 * A_ST)
#define BS0_OFF (2 * 64 * A_ST)
#define BS1_OFF (2 * 64 * A_ST + 256 * A_ST)
#define SMEM_ELEMS (2 * 64 * A_ST + 2 * 256 * A_ST)   // 25600 bf16 = 51200 B

__global__ __launch_bounds__(256, 1)
void draft_gemm_kernel(const float* __restrict__ A, float* __restrict__ C)
{
    __shared__ __align__(16) __nv_bfloat16 smem[SMEM_ELEMS];

    const int tid  = threadIdx.x;
    const int lane = tid & 31;
    const int warp = tid >> 5;
    const int wm   = warp >> 2;       // 0..1
    const int wn   = warp & 3;        // 0..3
    const int rowBase = blockIdx.x * BMD;

    const uint32_t sb = (uint32_t)__cvta_generic_to_shared(smem);

    float acc[2][8][4];
#pragma unroll
    for (int mt = 0; mt < 2; mt++)
#pragma unroll
        for (int nt = 0; nt < 8; nt++)
#pragma unroll
            for (int q = 0; q < 4; q++) acc[mt][nt][q] = 0.0f;

    // ldmatrix per-lane row/col offsets within a 16x16 tile
    const int a_row = (lane & 7) + ((lane >> 3) & 1) * 8;
    const int a_col = ((lane >> 4) & 1) * 8;
    const int b_row = (lane & 7) + ((lane >> 4) & 1) * 8;
    const int b_col = ((lane >> 3) & 1) * 8;

    for (int c = 0; c < HIDDEN / BKD; ++c) {
        const int kbase = c * BKD;

        // --- load + split A chunk: 64x32 f32 -> As0/As1 (2 float4/thread) ---
#pragma unroll
        for (int u = 0; u < 2; u++) {
            const int f   = tid * 2 + u;          // 0..511
            const int row = f >> 3;
            const int c4  = (f & 7) * 4;
            float4 v = *(const float4*)(A + (size_t)(rowBase + row) * HIDDEN + kbase + c4);
            float x[4] = {v.x, v.y, v.z, v.w};
#pragma unroll
            for (int j = 0; j < 4; j++) {
                __nv_bfloat16 h0 = __float2bfloat16_rn(x[j]);
                float r = x[j] - __bfloat162float(h0);
                __nv_bfloat16 h1 = __float2bfloat16_rn(r);
                smem[AS0_OFF + row * A_ST + c4 + j] = h0;
                smem[AS1_OFF + row * A_ST + c4 + j] = h1;
            }
        }

        // --- copy B chunk (precomputed bf16 splits): 256x32 per split ---
#pragma unroll
        for (int s = 0; s < 4; s++) {
            const int u   = s * 256 + tid;        // 0..1023
            const int row = u >> 2;
            const int seg = (u & 3) * 8;          // bf16 col offset (16B units)
            uint4 p0 = *(const uint4*)(d_b0 + (size_t)row * HIDDEN + kbase + seg);
            uint4 p1 = *(const uint4*)(d_b1 + (size_t)row * HIDDEN + kbase + seg);
            uint2* q0 = (uint2*)(smem + BS0_OFF + row * A_ST + seg);
            uint2* q1 = (uint2*)(smem + BS1_OFF + row * A_ST + seg);
            q0[0] = make_uint2(p0.x, p0.y); q0[1] = make_uint2(p0.z, p0.w);
            q1[0] = make_uint2(p1.x, p1.y); q1[1] = make_uint2(p1.z, p1.w);
        }
        __syncthreads();

        // --- two k-steps of 16 ---
#pragma unroll
        for (int ks = 0; ks < 2; ks++) {
            uint32_t afr[2][2][4];   // [split][m-tile][4]
#pragma unroll
            for (int s2 = 0; s2 < 2; s2++) {
                const int base = s2 ? AS1_OFF : AS0_OFF;
#pragma unroll
                for (int mt = 0; mt < 2; mt++) {
                    const int elem = base + (wm * 32 + mt * 16 + a_row) * A_ST
                                   + ks * 16 + a_col;
                    ldsm_x4(afr[s2][mt][0], afr[s2][mt][1],
                            afr[s2][mt][2], afr[s2][mt][3], sb + elem * 2);
                }
            }
            uint32_t bfr[2][4][4];   // [split][pair][t0b0,t0b1,t1b0,t1b1]
#pragma unroll
            for (int s2 = 0; s2 < 2; s2++) {
                const int base = s2 ? BS1_OFF : BS0_OFF;
#pragma unroll
                for (int p = 0; p < 4; p++) {
                    const int elem = base + (wn * 64 + p * 16 + b_row) * A_ST
                                   + ks * 16 + b_col;
                    ldsm_x4(bfr[s2][p][0], bfr[s2][p][1],
                            bfr[s2][p][2], bfr[s2][p][3], sb + elem * 2);
                }
            }
            // products: a0*b0 + a0*b1 + a1*b0
#pragma unroll
            for (int mt = 0; mt < 2; mt++)
#pragma unroll
                for (int p = 0; p < 4; p++)
#pragma unroll
                    for (int t = 0; t < 2; t++) {
                        float* cc = acc[mt][p * 2 + t];
                        mma16816(cc, afr[0][mt], bfr[0][p][t*2], bfr[0][p][t*2+1]);
                        mma16816(cc, afr[0][mt], bfr[1][p][t*2], bfr[1][p][t*2+1]);
                        mma16816(cc, afr[1][mt], bfr[0][p][t*2], bfr[0][p][t*2+1]);
                    }
        }
        __syncthreads();
    }

    // epilogue
#pragma unroll
    for (int mt = 0; mt < 2; mt++) {
        const int r0 = rowBase + wm * 32 + mt * 16 + (lane >> 2);
#pragma unroll
        for (int nt = 0; nt < 8; nt++) {
            const int col = wn * 64 + nt * 8 + (lane & 3) * 2;
            float2 v0 = make_float2(acc[mt][nt][0], acc[mt][nt][1]);
            float2 v1 = make_float2(acc[mt][nt][2], acc[mt][nt][3]);
            *(float2*)(C + (size_t)r0 * N_EXPERTS + col)       = v0;
            *(float2*)(C + (size_t)(r0 + 8) * N_EXPERTS + col) = v1;
        }
    }
}

// ---------------------------------------------------------------------------
// Routing on draft logits + near-tie flagging. One block per token.
// ---------------------------------------------------------------------------
__global__ __launch_bounds__(256)
void routing_kernel(const float* __restrict__ logits,
                    const float* __restrict__ bias,
                    float* __restrict__ out_idx,
                    float* __restrict__ out_w)
{
    const int token = blockIdx.x;
    const int tid   = threadIdx.x;
    const int lane  = tid & 31;
    const int warp  = tid >> 5;

    __shared__ float sraw[N_EXPERTS];
    __shared__ float sc[N_EXPERTS];
    __shared__ float gscore[N_GROUP];
    __shared__ int   gmask[N_GROUP];
    __shared__ int   selidx[TOP_K];
    __shared__ float selsc[TOP_K];
    __shared__ float gmargin_sh;

    const float L = logits[(size_t)token * N_EXPERTS + tid];
    const float s = ref_sigmoid(L);
    const float r = __fadd_rn(s, bias[tid]);
    sraw[tid] = s;

    // group top-2
    float a = r, b = -INFINITY;
#pragma unroll
    for (int off = 16; off; off >>= 1) {
        float oa = __shfl_xor_sync(0xffffffffu, a, off);
        float ob = __shfl_xor_sync(0xffffffffu, b, off);
        if (oa > a) { b = fmaxf(a, ob); a = oa; }
        else        { b = fmaxf(b, oa); }
    }
    if (lane == 0) gscore[warp] = __fadd_rn(a, b);
    __syncthreads();

    // top-4 groups + margin
    if (tid == 0) {
        float g[N_GROUP];
#pragma unroll
        for (int i = 0; i < N_GROUP; i++) g[i] = gscore[i];
        int chosen = 0; float g4 = 0.0f;
#pragma unroll
        for (int sel = 0; sel < TOPK_GROUP; sel++) {
            float best = -INFINITY; int bi = 0;
            for (int i = 0; i < N_GROUP; i++)
                if (!((chosen >> i) & 1) && g[i] > best) { best = g[i]; bi = i; }
            chosen |= (1 << bi);
            if (sel == TOPK_GROUP - 1) g4 = best;
        }
        float g5 = -INFINITY;
        for (int i = 0; i < N_GROUP; i++)
            if (!((chosen >> i) & 1)) g5 = fmaxf(g5, g[i]);
        gmargin_sh = g4 - g5;
#pragma unroll
        for (int i = 0; i < N_GROUP; i++) gmask[i] = (chosen >> i) & 1;
    }
    __syncthreads();

    sc[tid] = gmask[warp] ? r : -INFINITY;
    __syncthreads();

    if (warp == 0) {
        float v[8];
#pragma unroll
        for (int j = 0; j < 8; j++) v[j] = sc[j * 32 + lane];

        float prev = 0.0f, mingap = INFINITY;
#pragma unroll
        for (int it = 0; it < TOP_K + 1; it++) {
            float bv = -INFINITY; int bj = 0;
#pragma unroll
            for (int j = 0; j < 8; j++)
                if (v[j] > bv) { bv = v[j]; bj = j; }
            float mv = bv;
            int   mi = bj * 32 + lane;
#pragma unroll
            for (int off = 16; off; off >>= 1) {
                float ov = __shfl_xor_sync(0xffffffffu, mv, off);
                int   oi = __shfl_xor_sync(0xffffffffu, mi, off);
                if (ov > mv || (ov == mv && oi < mi)) { mv = ov; mi = oi; }
            }
#pragma unroll
            for (int j = 0; j < 8; j++)
                if (mi == j * 32 + lane) v[j] = -INFINITY;
            if (it < TOP_K && lane == it) selidx[it] = mi;
            if (it > 0) mingap = fminf(mingap, prev - mv);
            prev = mv;
        }

        if (lane == 0 && (mingap < TAU_E || gmargin_sh < TAU_G)) {
            int pos = atomicAdd(&d_fix_count, 1);
            if (pos < N_TOKENS) d_fix_list[pos] = token;
        }
        __syncwarp();

        if (lane < TOP_K) selsc[lane] = sraw[selidx[lane]];
        __syncwarp();

        if (lane < TOP_K) {
            float sum = selsc[0];
#pragma unroll
            for (int j = 1; j < TOP_K; j++) sum = __fadd_rn(sum, selsc[j]);
            const float w = __fmul_rn(
                __fdiv_rn(selsc[lane], __fadd_rn(sum, 1e-20f)), ROUTED_SCALING);
            out_idx[(size_t)token * TOP_K + lane] = (float)selidx[lane];
            out_w  [(size_t)token * TOP_K + lane] = w;
        }
    }
}

// ---------------------------------------------------------------------------
// Fixup: bit-exact reference pipeline (kc=320 serial fma chain) for flagged
// tokens. One thread per expert; grid-stride over flag list.
// ---------------------------------------------------------------------------
__global__ __launch_bounds__(256)
void fixup_kernel(const float* __restrict__ hs,
                  const float* __restrict__ wmat,
                  const float* __restrict__ bias,
                  float* __restrict__ out_idx,
                  float* __restrict__ out_w)
{
    const int tid  = threadIdx.x;
    const int lane = tid & 31;
    const int warp = tid >> 5;

    __shared__ float hsh[HIDDEN];
    __shared__ float sraw[N_EXPERTS];
    __shared__ float sc[N_EXPERTS];
    __shared__ float gscore[N_GROUP];
    __shared__ int   gmask[N_GROUP];
    __shared__ int   selidx[TOP_K];
    __shared__ float selsc[TOP_K];

    const int count = d_fix_count < N_TOKENS ? d_fix_count : N_TOKENS;

    for (int fi = blockIdx.x; fi < count; fi += gridDim.x) {
        const int token = d_fix_list[fi];

        for (int i = tid; i < HIDDEN; i += 256)
            hsh[i] = hs[(size_t)token * HIDDEN + i];
        __syncthreads();

        // exact logit: kc=320 panels, serial fused fma within, fadd joins
        const float4* w4 = (const float4*)(wmat + (size_t)tid * HIDDEN);
        const float4* h4 = (const float4*)hsh;
        float cur = 0.0f, tot = 0.0f;
        for (int q = 0; q < HIDDEN / 4; q++) {
            float4 wv = w4[q];
            float4 hv = h4[q];
            cur = fmaf(hv.x, wv.x, cur);
            cur = fmaf(hv.y, wv.y, cur);
            cur = fmaf(hv.z, wv.z, cur);
            cur = fmaf(hv.w, wv.w, cur);
            if (((q + 1) % 80) == 0 && q < 480) {   // k = 320,640,...,1920
                tot = __fadd_rn(tot, cur);
                cur = 0.0f;
            }
        }
        const float L = __fadd_rn(tot, cur);

        const float s = ref_sigmoid(L);
        const float r = __fadd_rn(s, bias[tid]);
        sraw[tid] = s;

        // group top-2
        float a = r, b = -INFINITY;
#pragma unroll
        for (int off = 16; off; off >>= 1) {
            float oa = __shfl_xor_sync(0xffffffffu, a, off);
            float ob = __shfl_xor_sync(0xffffffffu, b, off);
            if (oa > a) { b = fmaxf(a, ob); a = oa; }
            else        { b = fmaxf(b, oa); }
        }
        if (lane == 0) gscore[warp] = __fadd_rn(a, b);
        __syncthreads();

        if (tid == 0) {
            float g[N_GROUP];
#pragma unroll
            for (int i = 0; i < N_GROUP; i++) g[i] = gscore[i];
            int chosen = 0;
#pragma unroll
            for (int sel = 0; sel < TOPK_GROUP; sel++) {
                float best = -INFINITY; int bi = 0;
                for (int i = 0; i < N_GROUP; i++)
                    if (!((chosen >> i) & 1) && g[i] > best) { best = g[i]; bi = i; }
                chosen |= (1 << bi);
            }
#pragma unroll
            for (int i = 0; i < N_GROUP; i++) gmask[i] = (chosen >> i) & 1;
        }
        __syncthreads();

        sc[tid] = gmask[warp] ? r : -INFINITY;
        __syncthreads();

        if (warp == 0) {
            float v[8];
#pragma unroll
            for (int j = 0; j < 8; j++) v[j] = sc[j * 32 + lane];

#pragma unroll
            for (int it = 0; it < TOP_K; it++) {
                float bv = -INFINITY; int bj = 0;
#pragma unroll
                for (int j = 0; j < 8; j++)
                    if (v[j] > bv) { bv = v[j]; bj = j; }
                float mv = bv;
                int   mi = bj * 32 + lane;
#pragma unroll
                for (int off = 16; off; off >>= 1) {
                    float ov = __shfl_xor_sync(0xffffffffu, mv, off);
                    int   oi = __shfl_xor_sync(0xffffffffu, mi, off);
                    if (ov > mv || (ov == mv && oi < mi)) { mv = ov; mi = oi; }
                }
#pragma unroll
                for (int j = 0; j < 8; j++)
                    if (mi == j * 32 + lane) v[j] = -INFINITY;
                if (lane == it) selidx[it] = mi;
            }
            __syncwarp();

            if (lane < TOP_K) selsc[lane] = sraw[selidx[lane]];
            __syncwarp();

            if (lane < TOP_K) {
                float sum = selsc[0];
#pragma unroll
                for (int j = 1; j < TOP_K; j++) sum = __fadd_rn(sum, selsc[j]);
                const float w = __fmul_rn(
                    __fdiv_rn(selsc[lane], __fadd_rn(sum, 1e-20f)), ROUTED_SCALING);
                out_idx[(size_t)token * TOP_K + lane] = (float)selidx[lane];
                out_w  [(size_t)token * TOP_K + lane] = w;
            }
        }
        __syncthreads();
    }
}

// ---------------------------------------------------------------------------
extern "C" void kernel_launch(void* const* d_in, const int* in_sizes, int n_in,
                              void* d_out, int out_size)
{
    const float* hs   = (const float*)d_in[0];
    const float* w    = (const float*)d_in[1];
    const float* bias = (const float*)d_in[2];

    float* out = (float*)d_out;
    float* out_idx    = out;
    float* out_w      = out + (size_t)N_TOKENS * TOP_K;
    float* out_logits = out + (size_t)N_TOKENS * TOP_K * 2;

    reset_kernel<<<1, 1>>>();
    split_b_kernel<<<(N_EXPERTS * HIDDEN / 4) / 256, 256>>>(w);
    draft_gemm_kernel<<<N_TOKENS / BMD, 256>>>(hs, out_logits);
    routing_kernel<<<N_TOKENS, 256>>>(out_logits, bias, out_idx, out_w);
    fixup_kernel<<<FIX_GRID, 256>>>(hs, w, bias, out_idx, out_w);
}

// round 12
// speedup vs baseline: 4.1103x; 4.1103x over previous
#include <cuda_runtime.h>
#include <cuda_bf16.h>
#include <math.h>
#include <stdint.h>

// Problem constants
#define N_TOKENS   32768
#define HIDDEN     2048
#define N_EXPERTS  256
#define N_GROUP    8
#define TOPK_GROUP 4
#define TOP_K      8
#define ROUTED_SCALING 2.5f

// GEMM config: BM=128 rows, BN=256 cols (all experts), BK=8.
// 256 threads, per-thread 8 rows x 16 cols (8 fma2 col-pairs).
#define BM 128
#define BN 256
#define BK 8
#define NTILES (HIDDEN / BK)     // 256
#define FLUSH_PERIOD 40          // kc=320 / BK
#define TOT_ST 260               // padded tot row stride (floats)

// dynamic smem layout (floats)
#define OFF_AS0 0
#define OFF_AS1 (BK * BM)
#define OFF_BS0 (2 * BK * BM)
#define OFF_BS1 (2 * BK * BM + BK * BN)
#define OFF_TOT (2 * BK * BM + 2 * BK * BN)
#define SMEM_FLOATS (OFF_TOT + BM * TOT_ST)
#define SMEM_BYTES  (SMEM_FLOATS * 4)   // 157,696 B

typedef unsigned long long u64;

// ---------------------------------------------------------------------------
// Packed f32x2 helpers — each lane IEEE rn, bit-identical to scalar chains.
// ---------------------------------------------------------------------------
__device__ __forceinline__ u64 pack2(float lo, float hi) {
    u64 r;
    asm("mov.b64 %0, {%1, %2};" : "=l"(r) : "f"(lo), "f"(hi));
    return r;
}
__device__ __forceinline__ void unpack2(u64 v, float& lo, float& hi) {
    asm("mov.b64 {%0, %1}, %2;" : "=f"(lo), "=f"(hi) : "l"(v));
}
__device__ __forceinline__ void fma2(u64& d, u64 a, u64 b) {
    asm("fma.rn.f32x2 %0, %1, %2, %0;" : "+l"(d) : "l"(a), "l"(b));
}
__device__ __forceinline__ void add2(u64& d, u64 a) {
    asm("add.rn.f32x2 %0, %0, %1;" : "+l"(d) : "l"(a));
}

// ---------------------------------------------------------------------------
// XLA CPU GenerateVF32Exp (Cephes) — bit-pinned reference sigmoid.
// ---------------------------------------------------------------------------
__device__ __forceinline__ float xla_expf(float v) {
    float x = fminf(fmaxf(v, -88.3762626647949f), 88.3762626647950f);
    float fx = floorf(fmaf(x, 1.44269504088896341f, 0.5f));
    float tmp = __fmul_rn(fx, 0.693359375f);
    float z2  = __fmul_rn(fx, -2.12194440e-4f);
    x = __fsub_rn(x, tmp);
    x = __fsub_rn(x, z2);
    float zz = __fmul_rn(x, x);
    float y = 1.9875691500E-4f;
    y = fmaf(y, x, 1.3981999507E-3f);
    y = fmaf(y, x, 8.3334519073E-3f);
    y = fmaf(y, x, 4.1665795894E-2f);
    y = fmaf(y, x, 1.6666665459E-1f);
    y = fmaf(y, x, 5.0000001201E-1f);
    y = fmaf(y, zz, x);
    y = __fadd_rn(y, 1.0f);
    int n = (int)fx;
    float p2n = __int_as_float((n + 127) << 23);
    return __fmul_rn(y, p2n);
}
__device__ __forceinline__ float ref_sigmoid(float L) {
    return __fdiv_rn(1.0f, __fadd_rn(1.0f, xla_expf(-L)));
}

// ---------------------------------------------------------------------------
// GEMM: C[M,E] = A[M,K] * B[E,K]^T, fp32, FFMA2 (2 cols per 64-bit acc).
// Bit-exact Eigen gebp emulation: per element one serial fma chain within
// kc=320 panels (flush to smem tot every 40 tiles), panels joined by fadd.
// ---------------------------------------------------------------------------
__global__ __launch_bounds__(256, 1)
void gate_gemm_kernel(const float* __restrict__ A,
                      const float* __restrict__ B,
                      float* __restrict__ C)
{
    extern __shared__ float sm[];
    float* tot = sm + OFF_TOT;

    const int tid = threadIdx.x;
    const int tx  = tid & 15;          // 16 col groups
    const int ty  = tid >> 4;          // 16 row groups x 8 rows
    const int rowBase = blockIdx.x * BM;

    // loader indices
    const int ar = tid & 127;          // A row within tile
    const int ac = (tid >> 7) * 4;     // A k-offset (0 or 4)
    const int br = tid;                // B row (expert) 0..255

    const float* Aptr = A + (size_t)(rowBase + ar) * HIDDEN + ac;
    const float* Bptr = B + (size_t)br * HIDDEN;

    u64 cur[8][8];
#pragma unroll
    for (int i = 0; i < 8; i++)
#pragma unroll
        for (int p = 0; p < 8; p++) cur[i][p] = 0ull;

    // prologue: load + stage tile 0 into buffer 0
    {
        float4 pa  = *(const float4*)(Aptr);
        float4 pb0 = *(const float4*)(Bptr);
        float4 pb1 = *(const float4*)(Bptr + 4);
        float* As = sm + OFF_AS0;
        float* Bs = sm + OFF_BS0;
        As[(ac + 0) * BM + ar] = pa.x; As[(ac + 1) * BM + ar] = pa.y;
        As[(ac + 2) * BM + ar] = pa.z; As[(ac + 3) * BM + ar] = pa.w;
        Bs[0 * BN + br] = pb0.x; Bs[1 * BN + br] = pb0.y;
        Bs[2 * BN + br] = pb0.z; Bs[3 * BN + br] = pb0.w;
        Bs[4 * BN + br] = pb1.x; Bs[5 * BN + br] = pb1.y;
        Bs[6 * BN + br] = pb1.z; Bs[7 * BN + br] = pb1.w;
    }
    __syncthreads();

    for (int t = 0; t < NTILES; ++t) {
        const int buf = t & 1;

        // prefetch next tile into registers (latency hidden by compute)
        float4 na, nb0, nb1;
        if (t + 1 < NTILES) {
            const int k = (t + 1) * BK;
            na  = *(const float4*)(Aptr + k);
            nb0 = *(const float4*)(Bptr + k);
            nb1 = *(const float4*)(Bptr + k + 4);
        }

        const float* As = sm + (buf ? OFF_AS1 : OFF_AS0);
        const float* Bs = sm + (buf ? OFF_BS1 : OFF_BS0);

#pragma unroll
        for (int kk = 0; kk < BK; kk++) {
            float4 ra0 = *(const float4*)&As[kk * BM + ty * 8];
            float4 ra1 = *(const float4*)&As[kk * BM + ty * 8 + 4];
            float4 rb0 = *(const float4*)&Bs[kk * BN +   0 + tx * 4];
            float4 rb1 = *(const float4*)&Bs[kk * BN +  64 + tx * 4];
            float4 rb2 = *(const float4*)&Bs[kk * BN + 128 + tx * 4];
            float4 rb3 = *(const float4*)&Bs[kk * BN + 192 + tx * 4];

            u64 b2[8];
            b2[0] = pack2(rb0.x, rb0.y); b2[1] = pack2(rb0.z, rb0.w);
            b2[2] = pack2(rb1.x, rb1.y); b2[3] = pack2(rb1.z, rb1.w);
            b2[4] = pack2(rb2.x, rb2.y); b2[5] = pack2(rb2.z, rb2.w);
            b2[6] = pack2(rb3.x, rb3.y); b2[7] = pack2(rb3.z, rb3.w);

            float ra[8];
            ra[0]=ra0.x; ra[1]=ra0.y; ra[2]=ra0.z; ra[3]=ra0.w;
            ra[4]=ra1.x; ra[5]=ra1.y; ra[6]=ra1.z; ra[7]=ra1.w;
#pragma unroll
            for (int i = 0; i < 8; i++) {
                u64 a2 = pack2(ra[i], ra[i]);
#pragma unroll
                for (int p = 0; p < 8; p++)
                    fma2(cur[i][p], a2, b2[p]);
            }
        }

        // kc=320 panel flush: after tiles 39, 79, ..., 239
        if ((t % FLUSH_PERIOD) == (FLUSH_PERIOD - 1) && t < 240) {
            const bool first = (t < FLUSH_PERIOD);
#pragma unroll
            for (int i = 0; i < 8; i++) {
                const int row = ty * 8 + i;
#pragma unroll
                for (int p = 0; p < 8; p++) {
                    const int g = p >> 1;
                    u64* tp = (u64*)&tot[row * TOT_ST + g * 64 + tx * 4 + (p & 1) * 2];
                    if (first) {
                        *tp = cur[i][p];
                    } else {
                        u64 v = *tp;
                        add2(v, cur[i][p]);
                        *tp = v;
                    }
                    cur[i][p] = 0ull;
                }
            }
        }

        // stage next tile
        if (t + 1 < NTILES) {
            float* Asn = sm + (buf ? OFF_AS0 : OFF_AS1);
            float* Bsn = sm + (buf ? OFF_BS0 : OFF_BS1);
            Asn[(ac + 0) * BM + ar] = na.x; Asn[(ac + 1) * BM + ar] = na.y;
            Asn[(ac + 2) * BM + ar] = na.z; Asn[(ac + 3) * BM + ar] = na.w;
            Bsn[0 * BN + br] = nb0.x; Bsn[1 * BN + br] = nb0.y;
            Bsn[2 * BN + br] = nb0.z; Bsn[3 * BN + br] = nb0.w;
            Bsn[4 * BN + br] = nb1.x; Bsn[5 * BN + br] = nb1.y;
            Bsn[6 * BN + br] = nb1.z; Bsn[7 * BN + br] = nb1.w;
            __syncthreads();
        }
    }

    // final: logits = tot + cur (tail panel, k 1920-2047), write C
#pragma unroll
    for (int i = 0; i < 8; i++) {
        const int row = ty * 8 + i;
#pragma unroll
        for (int g = 0; g < 4; g++) {
            u64 t0 = *(u64*)&tot[row * TOT_ST + g * 64 + tx * 4];
            u64 t1 = *(u64*)&tot[row * TOT_ST + g * 64 + tx * 4 + 2];
            add2(t0, cur[i][2 * g]);
            add2(t1, cur[i][2 * g + 1]);
            float c0, c1, c2, c3;
            unpack2(t0, c0, c1);
            unpack2(t1, c2, c3);
            *(float4*)&C[(size_t)(rowBase + row) * N_EXPERTS + g * 64 + tx * 4] =
                make_float4(c0, c1, c2, c3);
        }
    }
}

// ---------------------------------------------------------------------------
// Routing (bit-pinned, validated R7/R8). One block (256 threads) per token.
// ---------------------------------------------------------------------------
__global__ __launch_bounds__(256)
void routing_kernel(const float* __restrict__ logits,
                    const float* __restrict__ bias,
                    float* __restrict__ out_idx,
                    float* __restrict__ out_w)
{
    const int token = blockIdx.x;
    const int tid   = threadIdx.x;
    const int lane  = tid & 31;
    const int warp  = tid >> 5;

    __shared__ float sraw[N_EXPERTS];
    __shared__ float sc[N_EXPERTS];
    __shared__ float gscore[N_GROUP];
    __shared__ int   gmask[N_GROUP];
    __shared__ int   selidx[TOP_K];
    __shared__ float selsc[TOP_K];

    const float L = logits[(size_t)token * N_EXPERTS + tid];
    const float s = ref_sigmoid(L);
    const float r = __fadd_rn(s, bias[tid]);
    sraw[tid] = s;

    // group top-2 (warp = group); group score = a + b, a >= b
    float a = r, b = -INFINITY;
#pragma unroll
    for (int off = 16; off; off >>= 1) {
        float oa = __shfl_xor_sync(0xffffffffu, a, off);
        float ob = __shfl_xor_sync(0xffffffffu, b, off);
        if (oa > a) { b = fmaxf(a, ob); a = oa; }
        else        { b = fmaxf(b, oa); }
    }
    if (lane == 0) gscore[warp] = __fadd_rn(a, b);
    __syncthreads();

    // top-4 groups, tie -> lower index
    if (tid == 0) {
        float g[N_GROUP];
#pragma unroll
        for (int i = 0; i < N_GROUP; i++) g[i] = gscore[i];
        int chosen = 0;
#pragma unroll
        for (int sel = 0; sel < TOPK_GROUP; sel++) {
            float best = -INFINITY; int bi = 0;
            for (int i = 0; i < N_GROUP; i++)
                if (!((chosen >> i) & 1) && g[i] > best) { best = g[i]; bi = i; }
            chosen |= (1 << bi);
        }
#pragma unroll
        for (int i = 0; i < N_GROUP; i++) gmask[i] = (chosen >> i) & 1;
    }
    __syncthreads();

    sc[tid] = gmask[warp] ? r : -INFINITY;
    __syncthreads();

    // top-8 experts (warp 0), stable tie-break
    if (warp == 0) {
        float v[8];
#pragma unroll
        for (int j = 0; j < 8; j++) v[j] = sc[j * 32 + lane];

#pragma unroll
        for (int it = 0; it < TOP_K; it++) {
            float bv = -INFINITY; int bj = 0;
#pragma unroll
            for (int j = 0; j < 8; j++)
                if (v[j] > bv) { bv = v[j]; bj = j; }   // tie -> lower j
            float mv = bv;
            int   mi = bj * 32 + lane;
#pragma unroll
            for (int off = 16; off; off >>= 1) {
                float ov = __shfl_xor_sync(0xffffffffu, mv, off);
                int   oi = __shfl_xor_sync(0xffffffffu, mi, off);
                if (ov > mv || (ov == mv && oi < mi)) { mv = ov; mi = oi; }
            }
#pragma unroll
            for (int j = 0; j < 8; j++)
                if (mi == j * 32 + lane) v[j] = -INFINITY;
            if (lane == it) selidx[it] = mi;
        }
        __syncwarp();

        if (lane < TOP_K) selsc[lane] = sraw[selidx[lane]];
        __syncwarp();

        if (lane < TOP_K) {
            float sum = selsc[0];
#pragma unroll
            for (int j = 1; j < TOP_K; j++) sum = __fadd_rn(sum, selsc[j]);
            const float w = __fmul_rn(
                __fdiv_rn(selsc[lane], __fadd_rn(sum, 1e-20f)), ROUTED_SCALING);
            out_idx[(size_t)token * TOP_K + lane] = (float)selidx[lane];
            out_w  [(size_t)token * TOP_K + lane] = w;
        }
    }
}

// ---------------------------------------------------------------------------
extern "C" void kernel_launch(void* const* d_in, const int* in_sizes, int n_in,
                              void* d_out, int out_size)
{
    const float* hs   = (const float*)d_in[0];
    const float* w    = (const float*)d_in[1];
    const float* bias = (const float*)d_in[2];

    float* out = (float*)d_out;
    float* out_idx    = out;
    float* out_w      = out + (size_t)N_TOKENS * TOP_K;
    float* out_logits = out + (size_t)N_TOKENS * TOP_K * 2;

    cudaFuncSetAttribute(gate_gemm_kernel,
                         cudaFuncAttributeMaxDynamicSharedMemorySize, SMEM_BYTES);

    gate_gemm_kernel<<<N_TOKENS / BM, 256, SMEM_BYTES>>>(hs, w, out_logits);
    routing_kernel<<<N_TOKENS, 256>>>(out_logits, bias, out_idx, out_w);
}